// round 3
// baseline (speedup 1.0000x reference)
#include <cuda_runtime.h>
#include <cstdint>

typedef unsigned long long ull;

#define NB     16
#define DD     128
#define NENT   100000
#define NTILES 3125          // NENT / 32
#define GRID   296           // 2 blocks per SM
#define TPB    192           // 6 warps
#define NW     6
// dynamic smem: hs (16*128 floats = 8KB) + 6 warps * 32 rows * 32 float4 (16KB each)
#define SMEM_BYTES (8192 + NW * 32 * 32 * 16)

// ---------------- device scratch (allocation-free, zero-init) ----------------
__device__ float    g_part[NB * GRID];
__device__ unsigned g_ctr;
__device__ unsigned g_done;

// ---------------- packed f32x2 helpers (sm_103a) ----------------
__device__ __forceinline__ ull add2(ull a, ull b) {
    ull r; asm("add.rn.f32x2 %0,%1,%2;" : "=l"(r) : "l"(a), "l"(b)); return r;
}
__device__ __forceinline__ ull fma2(ull a, ull b, ull c) {
    ull r; asm("fma.rn.f32x2 %0,%1,%2,%3;" : "=l"(r) : "l"(a), "l"(b), "l"(c)); return r;
}
__device__ __forceinline__ ull abs2(ull a) {
    return a & 0x7FFFFFFF7FFFFFFFull;
}
__device__ __forceinline__ ull pk2(float a, float b) {
    ull r; asm("mov.b64 %0,{%1,%2};" : "=l"(r) : "f"(a), "f"(b)); return r;
}
__device__ __forceinline__ float2 upk(ull a) {
    float2 f; asm("mov.b64 {%0,%1},%2;" : "=f"(f.x), "=f"(f.y) : "l"(a)); return f;
}
__device__ __forceinline__ float wsum(float v) {
    #pragma unroll
    for (int o = 16; o; o >>= 1) v += __shfl_xor_sync(0xffffffffu, v, o);
    return v;
}

// =============== kernel 1: h build + dist -> exp -> store + partial sums ===============
__global__ void __launch_bounds__(TPB, 2)
k_dist(const float* __restrict__ ent, const float* __restrict__ relemb,
       const int* __restrict__ e1w, const int* __restrict__ relw,
       float* __restrict__ out) {
    extern __shared__ float smf[];
    float*      hs  = smf;                                // 2048 floats
    ulonglong2* hs2 = (ulonglong2*)smf;                   // [16][32]
    int tid = threadIdx.x, w = tid >> 5, l = tid & 31;
    ulonglong2* xs2 = (ulonglong2*)(smf + 2048) + w * (32 * 32);
    float4*     xs4 = (float4*)xs2;

    __shared__ float sp[NW * NB];
    __shared__ int   s64;
    if (tid == 0) {
        // int64 detection: high 32-bit words all zero => int64 indices
        int o = e1w[1] | e1w[3] | e1w[5] | e1w[7] | e1w[9] | e1w[11] | e1w[13] | e1w[15];
        s64 = (o == 0);
    }
    __syncthreads();

    // ---- build h = norm(ent[e1[b]]) + norm(rel[rel[b]]) (per-block redundant) ----
    for (int b = w; b < NB; b += NW) {
        long long ei, ri;
        if (s64) { ei = ((const long long*)e1w)[b]; ri = ((const long long*)relw)[b]; }
        else     { ei = (long long)e1w[b];          ri = (long long)relw[b]; }
        float4 a = ((const float4*)ent)[(size_t)ei * 32 + l];
        float sa = wsum(fmaf(a.x, a.x, fmaf(a.y, a.y, fmaf(a.z, a.z, a.w * a.w))));
        float ia = rsqrtf(fmaxf(sa, 1e-24f));
        float4 c = ((const float4*)relemb)[(size_t)ri * 32 + l];
        float sc = wsum(fmaf(c.x, c.x, fmaf(c.y, c.y, fmaf(c.z, c.z, c.w * c.w))));
        float ic = rsqrtf(fmaxf(sc, 1e-24f));
        float4 h;
        h.x = fmaf(a.x, ia, c.x * ic);
        h.y = fmaf(a.y, ia, c.y * ic);
        h.z = fmaf(a.z, ia, c.z * ic);
        h.w = fmaf(a.w, ia, c.w * ic);
        ((float4*)hs)[b * 32 + l] = h;
    }
    __syncthreads();

    const int swz = l & 7;
    float esum[NB];
    #pragma unroll
    for (int b = 0; b < NB; b++) esum[b] = 0.0f;

    for (;;) {
        unsigned t = 0u;
        if (l == 0) t = atomicAdd(&g_ctr, 1u);
        t = __shfl_sync(0xffffffffu, t, 0);
        if (t >= (unsigned)NTILES) break;
        int base = (int)t * 32;
        const float4* rowp = (const float4*)ent + (size_t)base * 32 + l;

        __syncwarp();   // prior tile's smem reads done before overwrite
        // stage 32 rows, coalesced loads, swizzled stores (conflict-free, no pad)
        #pragma unroll
        for (int r0 = 0; r0 < 32; r0 += 8) {
            float4 v[8];
            #pragma unroll
            for (int r = 0; r < 8; r++) v[r] = rowp[(r0 + r) * 32];
            #pragma unroll
            for (int r = 0; r < 8; r++)
                xs4[(r0 + r) * 32 + (l ^ ((r0 + r) & 7))] = v[r];
        }
        __syncwarp();

        // sumsq of my entity row (lane l owns entity base+l)
        float s0 = 0.f, s1 = 0.f, s2 = 0.f, s3 = 0.f;
        #pragma unroll
        for (int j = 0; j < 32; j += 4) {
            float4 v0 = xs4[l * 32 + ((j + 0) ^ swz)];
            float4 v1 = xs4[l * 32 + ((j + 1) ^ swz)];
            float4 v2 = xs4[l * 32 + ((j + 2) ^ swz)];
            float4 v3 = xs4[l * 32 + ((j + 3) ^ swz)];
            s0 = fmaf(v0.x, v0.x, fmaf(v0.y, v0.y, fmaf(v0.z, v0.z, fmaf(v0.w, v0.w, s0))));
            s1 = fmaf(v1.x, v1.x, fmaf(v1.y, v1.y, fmaf(v1.z, v1.z, fmaf(v1.w, v1.w, s1))));
            s2 = fmaf(v2.x, v2.x, fmaf(v2.y, v2.y, fmaf(v2.z, v2.z, fmaf(v2.w, v2.w, s2))));
            s3 = fmaf(v3.x, v3.x, fmaf(v3.y, v3.y, fmaf(v3.z, v3.z, fmaf(v3.w, v3.w, s3))));
        }
        float ss  = (s0 + s1) + (s2 + s3);
        float inv = -rsqrtf(fmaxf(ss, 1e-24f));      // diff = fma(x, -inv, h)
        ull nInv = pk2(inv, inv);

        ull acc[NB];
        #pragma unroll
        for (int b = 0; b < NB; b++) acc[b] = 0ull;

        #pragma unroll 1
        for (int c = 0; c < 8; c++) {                // 8 chunks of 16 dims
            ull x[8];
            #pragma unroll
            for (int q = 0; q < 4; q++) {
                ulonglong2 xx = xs2[l * 32 + ((c * 4 + q) ^ swz)];
                x[2*q]   = xx.x;
                x[2*q+1] = xx.y;
            }
            #pragma unroll
            for (int b = 0; b < NB; b++) {
                const ulonglong2* hp = hs2 + b * 32 + c * 4;  // uniform -> broadcast
                #pragma unroll
                for (int q = 0; q < 4; q++) {
                    ulonglong2 hh = hp[q];
                    acc[b] = add2(acc[b], abs2(fma2(x[2*q],   nInv, hh.x)));
                    acc[b] = add2(acc[b], abs2(fma2(x[2*q+1], nInv, hh.y)));
                }
            }
        }

        // dist <= ~34 so exp(dist) is finite: softmax needs no max pass
        #pragma unroll
        for (int b = 0; b < NB; b++) {
            float2 f = upk(acc[b]);
            float e = __expf(f.x + f.y);
            out[b * NENT + base + l] = e;            // coalesced per b
            esum[b] += e;
        }
    }

    // per-warp -> per-block row sums
    #pragma unroll
    for (int b = 0; b < NB; b++) {
        float s = wsum(esum[b]);
        if (l == 0) sp[w * NB + b] = s;
    }
    __syncthreads();
    if (tid < NB) {
        float s = 0.f;
        #pragma unroll
        for (int ww = 0; ww < NW; ww++) s += sp[ww * NB + tid];
        g_part[tid * GRID + blockIdx.x] = s;
    }
    // last block resets the work-queue counter for the next graph replay
    if (tid == 0) {
        unsigned d = atomicAdd(&g_done, 1u);
        if (d == GRID - 1) { g_ctr = 0u; g_done = 0u; }
    }
}

// =============== kernel 2: pred = e / sum (sum reduced from per-block partials) ===============
__global__ void __launch_bounds__(256)
k_norm(float* __restrict__ out) {
    int b = blockIdx.y;
    __shared__ float sinv;
    if (threadIdx.x < 32) {
        float p = 0.f;
        for (int i = threadIdx.x; i < GRID; i += 32) p += g_part[b * GRID + i];
        p = wsum(p);
        if (threadIdx.x == 0) sinv = 1.0f / p;
    }
    __syncthreads();
    int i = blockIdx.x * blockDim.x + threadIdx.x;
    if (i < NENT / 4) {
        float4* o = (float4*)out + (size_t)b * (NENT / 4) + i;
        float4 v = *o;
        float s = sinv;
        v.x *= s; v.y *= s; v.z *= s; v.w *= s;
        *o = v;
    }
}

// ---------------- launch ----------------
extern "C" void kernel_launch(void* const* d_in, const int* in_sizes, int n_in,
                              void* d_out, int out_size) {
    const int*   e1     = (const int*)d_in[0];
    const int*   rel    = (const int*)d_in[1];
    // d_in[2]=X, d_in[3]=A unused by the forward pass
    const float* ent    = (const float*)d_in[4];
    const float* relemb = (const float*)d_in[5];
    float* out = (float*)d_out;

    cudaFuncSetAttribute(k_dist, cudaFuncAttributeMaxDynamicSharedMemorySize, SMEM_BYTES);

    k_dist<<<GRID, TPB, SMEM_BYTES>>>(ent, relemb, e1, rel, out);
    dim3 gn((NENT / 4 + 255) / 256, NB);
    k_norm<<<gn, 256>>>(out);
    (void)in_sizes; (void)n_in; (void)out_size;
}